// round 1
// baseline (speedup 1.0000x reference)
#include <cuda_runtime.h>
#include <math.h>

#define Bn 8
#define Hn 96
#define Wn 96
#define Dn 256
#define NPIX (Bn*Hn*Wn)          // 73728
#define NCH 96                    // chunks per sequence (= chunk length)

// ---------------- scratch (device globals; no allocation allowed) -------------
__device__ float g_xin[NPIX*Dn];
__device__ float g_gate[NPIX*Dn];
__device__ float g_u[NPIX*Dn];
__device__ float g_y[NPIX*Dn];
// [orient][0=fwd local final | 1=Total(=bwd local final)][b][chunk][c]
__device__ float g_fin[2][2][Bn][NCH][Dn];
// [orient][0=fwd carry-in | 1=bwd carry-in][b][chunk][c]
__device__ float g_carry[2][2][Bn][NCH][Dn];

__device__ __forceinline__ float sigmoidf_(float v){ return 1.f/(1.f+expf(-v)); }

// =============== K1: LayerNorm + in_proj GEMM (M=73728,K=256,N=512) ===========
// grid: (1152, 8), 256 thr. 64x64 tile, 4x4 microtile.
__global__ __launch_bounds__(256) void k_ln_inproj(
    const float* __restrict__ x, const float* __restrict__ ln_g,
    const float* __restrict__ ln_b, const float* __restrict__ w_in,
    const float* __restrict__ b_in)
{
    __shared__ float aS[64][33];
    __shared__ float wS[32][68];
    __shared__ float smu[64], srstd[64];
    __shared__ float sg[256], sbe[256];

    int tid = threadIdx.x, lane = tid & 31, warp = tid >> 5;
    int m0 = blockIdx.x * 64, n0 = blockIdx.y * 64;

    sg[tid] = ln_g[tid]; sbe[tid] = ln_b[tid];

    // LN stats: warp handles 8 rows
    for (int rr = 0; rr < 8; rr++) {
        int r = warp * 8 + rr;
        const float* xr = x + (size_t)(m0 + r) * Dn;
        float s = 0.f, s2 = 0.f;
        #pragma unroll
        for (int kk = 0; kk < 8; kk++) { float t = xr[kk*32 + lane]; s += t; s2 += t*t; }
        #pragma unroll
        for (int off = 16; off; off >>= 1) {
            s  += __shfl_xor_sync(0xffffffffu, s,  off);
            s2 += __shfl_xor_sync(0xffffffffu, s2, off);
        }
        if (lane == 0) {
            float mu = s * (1.f/256.f);
            smu[r] = mu;
            srstd[r] = rsqrtf(s2 * (1.f/256.f) - mu*mu + 1e-5f);
        }
    }
    __syncthreads();

    int tx = tid & 15, ty = tid >> 4;
    float acc[4][4] = {};

    for (int kc = 0; kc < 8; kc++) {
        __syncthreads();
        #pragma unroll
        for (int q = 0; q < 8; q++) {
            int lin = q*256 + tid;
            int r = lin >> 5, kk = lin & 31;
            int k = kc*32 + kk;
            float v = x[(size_t)(m0 + r) * Dn + k];
            aS[r][kk] = (v - smu[r]) * srstd[r] * sg[k] + sbe[k];
        }
        #pragma unroll
        for (int q = 0; q < 8; q++) {
            int lin = q*256 + tid;
            int kr = lin >> 6, nc = lin & 63;
            wS[kr][nc] = w_in[(size_t)(kc*32 + kr) * 512 + n0 + nc];
        }
        __syncthreads();
        #pragma unroll
        for (int k = 0; k < 32; k++) {
            float h0 = aS[ty*4+0][k], h1 = aS[ty*4+1][k];
            float h2 = aS[ty*4+2][k], h3 = aS[ty*4+3][k];
            float4 wv = *(const float4*)&wS[k][tx*4];
            acc[0][0] += h0*wv.x; acc[0][1] += h0*wv.y; acc[0][2] += h0*wv.z; acc[0][3] += h0*wv.w;
            acc[1][0] += h1*wv.x; acc[1][1] += h1*wv.y; acc[1][2] += h1*wv.z; acc[1][3] += h1*wv.w;
            acc[2][0] += h2*wv.x; acc[2][1] += h2*wv.y; acc[2][2] += h2*wv.z; acc[2][3] += h2*wv.w;
            acc[3][0] += h3*wv.x; acc[3][1] += h3*wv.y; acc[3][2] += h3*wv.z; acc[3][3] += h3*wv.w;
        }
    }

    bool isGate = (n0 >= 256);
    #pragma unroll
    for (int i = 0; i < 4; i++) {
        int row = m0 + ty*4 + i;
        #pragma unroll
        for (int jj = 0; jj < 4; jj++) {
            int n = n0 + tx*4 + jj;
            float v = acc[i][jj] + b_in[n];
            if (isGate) g_gate[(size_t)row * Dn + (n - 256)] = sigmoidf_(v);
            else        g_xin [(size_t)row * Dn + n] = v;
        }
    }
}

// =============== K2: depthwise 3x3 conv (SAME) + SiLU ========================
// grid: B*H = 768, 256 thr (channel). Sliding window over w.
__global__ __launch_bounds__(256) void k_conv(
    const float* __restrict__ conv_w, const float* __restrict__ conv_b)
{
    int c = threadIdx.x;
    int b = blockIdx.x / Hn, h = blockIdx.x % Hn;

    float kw[3][3];
    #pragma unroll
    for (int dh = 0; dh < 3; dh++)
        #pragma unroll
        for (int dw = 0; dw < 3; dw++)
            kw[dh][dw] = conv_w[(dh*3 + dw) * Dn + c];
    float bias = conv_b[c];

    const float* rp[3]; bool hv[3];
    #pragma unroll
    for (int dh = 0; dh < 3; dh++) {
        int hh = h + dh - 1;
        hv[dh] = (hh >= 0 && hh < Hn);
        rp[dh] = g_xin + ((size_t)(b*Hn + (hv[dh] ? hh : 0)) * Wn) * Dn + c;
    }

    float v[3][3];
    #pragma unroll
    for (int dh = 0; dh < 3; dh++) {
        v[dh][0] = 0.f;
        v[dh][1] = hv[dh] ? rp[dh][0]   : 0.f;
        v[dh][2] = hv[dh] ? rp[dh][Dn]  : 0.f;
    }

    float* up = g_u + ((size_t)(b*Hn + h) * Wn) * Dn + c;
    for (int w = 0; w < Wn; w++) {
        float s = bias;
        #pragma unroll
        for (int dh = 0; dh < 3; dh++)
            #pragma unroll
            for (int dw = 0; dw < 3; dw++)
                s += v[dh][dw] * kw[dh][dw];
        up[(size_t)w * Dn] = s * sigmoidf_(s);      // SiLU
        #pragma unroll
        for (int dh = 0; dh < 3; dh++) {
            v[dh][0] = v[dh][1]; v[dh][1] = v[dh][2];
            int wn = w + 2;
            v[dh][2] = (hv[dh] && wn < Wn) ? rp[dh][(size_t)wn * Dn] : 0.f;
        }
    }
}

// =============== K3a: per-chunk fwd local final + Total (single pass) ========
// grid: (96 chunks, 8 batch, 2 orient), 256 thr (channel)
__global__ __launch_bounds__(256) void k_scanA(
    const float* __restrict__ a_logit, const float* __restrict__ ssm_b)
{
    int c = threadIdx.x;
    int j = blockIdx.x, b = blockIdx.y, o = blockIdx.z;
    float a = fminf(fmaxf(sigmoidf_(a_logit[c]), 1e-4f), 1.f - 1e-4f);
    float bb = ssm_b[c];

    size_t base; size_t stride;
    if (o == 0) { base = ((size_t)(b*Hn + j) * Wn) * Dn + c;      stride = Dn; }
    else        { base = ((size_t)b*Hn*Wn + (size_t)j) * Dn + c;  stride = (size_t)Wn * Dn; }

    float lf = 0.f, P = 0.f, ap = 1.f;
    for (int i = 0; i < NCH; i++) {
        float ux = g_u[base + (size_t)i * stride];
        lf = a * lf + bb * ux;
        P += ap * bb * ux;
        ap *= a;
    }
    g_fin[o][0][b][j][c] = lf;   // fwd local final
    g_fin[o][1][b][j][c] = P;    // Total = bwd local final
}

// =============== K3b: chunk-level carry scans (96 steps) ======================
// grid: (8 batch, 2 orient), 256 thr
__global__ __launch_bounds__(256) void k_scanB(const float* __restrict__ a_logit)
{
    int c = threadIdx.x;
    int b = blockIdx.x, o = blockIdx.y;
    float a = fminf(fmaxf(sigmoidf_(a_logit[c]), 1e-4f), 1.f - 1e-4f);
    float a96 = (float)exp(96.0 * log((double)a));

    float carry = 0.f;
    for (int j = 0; j < NCH; j++) {
        g_carry[o][0][b][j][c] = carry;
        carry = a96 * carry + g_fin[o][0][b][j][c];
    }
    carry = 0.f;
    for (int j = NCH - 1; j >= 0; j--) {
        g_carry[o][1][b][j][c] = carry;
        carry = a96 * carry + g_fin[o][1][b][j][c];
    }
}

// =============== K3c: apply (fwd recurrence + suffix-trick bwd), accumulate ==
// grid: (96 chunks, 8 batch), 256 thr. o passed as param (launch twice).
__global__ __launch_bounds__(256) void k_scanC(
    const float* __restrict__ a_logit, const float* __restrict__ ssm_b,
    const float* __restrict__ ssm_c,  const float* __restrict__ ssm_d, int o)
{
    int c = threadIdx.x;
    int j = blockIdx.x, b = blockIdx.y;
    float a = fminf(fmaxf(sigmoidf_(a_logit[c]), 1e-4f), 1.f - 1e-4f);
    float inva = 1.f / a;
    float a96 = (float)exp(96.0 * log((double)a));
    float bb = ssm_b[c], cc = ssm_c[c], dd = ssm_d[c];

    float sf = g_carry[o][0][b][j][c];
    float cb96 = a96 * g_carry[o][1][b][j][c];
    float Total = g_fin[o][1][b][j][c];

    size_t base; size_t stride;
    if (o == 0) { base = ((size_t)(b*Hn + j) * Wn) * Dn + c;      stride = Dn; }
    else        { base = ((size_t)b*Hn*Wn + (size_t)j) * Dn + c;  stride = (size_t)Wn * Dn; }

    float P = 0.f, ap = 1.f, rap = 1.f;
    for (int i = 0; i < NCH; i++) {
        size_t addr = base + (size_t)i * stride;
        float ux = g_u[addr];
        sf = a * sf + bb * ux;                       // fwd state (incl. elem i)
        float sb = (Total - P + cb96) * rap;          // bwd state (incl. elem i)
        float contrib = 0.25f * cc * (sf + sb);
        if (o == 0) {
            g_y[addr] = contrib + dd * ux;            // d-term folded once (x2 dirs x2 orients x0.25 = 1)
        } else {
            g_y[addr] += contrib;
        }
        P += ap * bb * ux;
        ap *= a; rap *= inva;
    }
}

// =============== K4: gate * y -> out_proj GEMM + bias + residual ==============
// grid: (1152, 4), 256 thr. Same tiling as K1.
__global__ __launch_bounds__(256) void k_outproj(
    const float* __restrict__ x, const float* __restrict__ w_out,
    const float* __restrict__ b_out, float* __restrict__ out)
{
    __shared__ float aS[64][33];
    __shared__ float wS[32][68];
    int tid = threadIdx.x;
    int m0 = blockIdx.x * 64, n0 = blockIdx.y * 64;
    int tx = tid & 15, ty = tid >> 4;
    float acc[4][4] = {};

    for (int kc = 0; kc < 8; kc++) {
        __syncthreads();
        #pragma unroll
        for (int q = 0; q < 8; q++) {
            int lin = q*256 + tid;
            int r = lin >> 5, kk = lin & 31;
            size_t idx = (size_t)(m0 + r) * Dn + kc*32 + kk;
            aS[r][kk] = g_y[idx] * g_gate[idx];
        }
        #pragma unroll
        for (int q = 0; q < 8; q++) {
            int lin = q*256 + tid;
            int kr = lin >> 6, nc = lin & 63;
            wS[kr][nc] = w_out[(size_t)(kc*32 + kr) * Dn + n0 + nc];
        }
        __syncthreads();
        #pragma unroll
        for (int k = 0; k < 32; k++) {
            float h0 = aS[ty*4+0][k], h1 = aS[ty*4+1][k];
            float h2 = aS[ty*4+2][k], h3 = aS[ty*4+3][k];
            float4 wv = *(const float4*)&wS[k][tx*4];
            acc[0][0] += h0*wv.x; acc[0][1] += h0*wv.y; acc[0][2] += h0*wv.z; acc[0][3] += h0*wv.w;
            acc[1][0] += h1*wv.x; acc[1][1] += h1*wv.y; acc[1][2] += h1*wv.z; acc[1][3] += h1*wv.w;
            acc[2][0] += h2*wv.x; acc[2][1] += h2*wv.y; acc[2][2] += h2*wv.z; acc[2][3] += h2*wv.w;
            acc[3][0] += h3*wv.x; acc[3][1] += h3*wv.y; acc[3][2] += h3*wv.z; acc[3][3] += h3*wv.w;
        }
    }

    #pragma unroll
    for (int i = 0; i < 4; i++) {
        int row = m0 + ty*4 + i;
        #pragma unroll
        for (int jj = 0; jj < 4; jj++) {
            int n = n0 + tx*4 + jj;
            out[(size_t)row * Dn + n] = acc[i][jj] + b_out[n] + x[(size_t)row * Dn + n];
        }
    }
}

// ==============================================================================
extern "C" void kernel_launch(void* const* d_in, const int* in_sizes, int n_in,
                              void* d_out, int out_size)
{
    const float* x       = (const float*)d_in[0];
    const float* ln_g    = (const float*)d_in[1];
    const float* ln_b    = (const float*)d_in[2];
    const float* w_in    = (const float*)d_in[3];
    const float* b_in    = (const float*)d_in[4];
    const float* conv_w  = (const float*)d_in[5];
    const float* conv_b  = (const float*)d_in[6];
    const float* a_logit = (const float*)d_in[7];
    const float* ssm_b   = (const float*)d_in[8];
    const float* ssm_c   = (const float*)d_in[9];
    const float* ssm_d   = (const float*)d_in[10];
    const float* w_out   = (const float*)d_in[11];
    const float* b_out   = (const float*)d_in[12];
    float* out = (float*)d_out;

    k_ln_inproj<<<dim3(NPIX/64, 8), 256>>>(x, ln_g, ln_b, w_in, b_in);
    k_conv<<<Bn*Hn, 256>>>(conv_w, conv_b);
    k_scanA<<<dim3(NCH, Bn, 2), 256>>>(a_logit, ssm_b);
    k_scanB<<<dim3(Bn, 2), 256>>>(a_logit);
    k_scanC<<<dim3(NCH, Bn), 256>>>(a_logit, ssm_b, ssm_c, ssm_d, 0);
    k_scanC<<<dim3(NCH, Bn), 256>>>(a_logit, ssm_b, ssm_c, ssm_d, 1);
    k_outproj<<<dim3(NPIX/64, 4), 256>>>(x, w_out, b_out, out);
}

// round 2
// speedup vs baseline: 1.3404x; 1.3404x over previous
#include <cuda_runtime.h>
#include <math.h>

#define Bn 8
#define Hn 96
#define Wn 96
#define Dn 256
#define NPIX (Bn*Hn*Wn)          // 73728
#define NCH 96

typedef unsigned long long u64;

// ---------------- scratch (device globals) ------------------------------------
__device__ float g_xin[NPIX*Dn];
__device__ float g_gate[NPIX*Dn];
__device__ float g_u[NPIX*Dn];
__device__ float g_y[NPIX*Dn];
__device__ float g_fin[2][2][Bn][NCH][Dn];
__device__ float g_carry[2][2][Bn][NCH][Dn];

__device__ __forceinline__ float sigmoidf_(float v){ return 1.f/(1.f+expf(-v)); }

__device__ __forceinline__ u64 ffma2(u64 a, u64 b, u64 c){
    u64 d;
    asm("fma.rn.f32x2 %0, %1, %2, %3;" : "=l"(d) : "l"(a), "l"(b), "l"(c));
    return d;
}
__device__ __forceinline__ u64 pk2(float lo, float hi){
    u64 r;
    asm("mov.b64 %0, {%1, %2};" : "=l"(r) : "f"(lo), "f"(hi));
    return r;
}
__device__ __forceinline__ void upk2(u64 v, float& lo, float& hi){
    asm("mov.b64 {%0, %1}, %2;" : "=f"(lo), "=f"(hi) : "l"(v));
}

// =============== K1: LayerNorm + in_proj GEMM (M=73728,K=256,N=512) ===========
// grid: (4 nblk, 576 mblk), 256 thr. 128x128 tile, 8x8 microtile, FFMA2.
__global__ __launch_bounds__(256) void k_ln_inproj(
    const float* __restrict__ x, const float* __restrict__ ln_g,
    const float* __restrict__ ln_b, const float* __restrict__ w_in,
    const float* __restrict__ b_in)
{
    __shared__ u64   aS[16][130];   // [k][row] = {h,h}
    __shared__ float wS[16][132];   // [k][col]
    __shared__ float smu[128], srstd[128];
    __shared__ float sg[256], sbe[256];

    int tid = threadIdx.x, lane = tid & 31, warp = tid >> 5;
    int n0 = blockIdx.x * 128, m0 = blockIdx.y * 128;

    sg[tid] = ln_g[tid]; sbe[tid] = ln_b[tid];

    // LN stats: each warp does 16 rows
    for (int rr = 0; rr < 16; rr++) {
        int r = warp * 16 + rr;
        const float* xr = x + (size_t)(m0 + r) * Dn;
        float s = 0.f, s2 = 0.f;
        #pragma unroll
        for (int kk = 0; kk < 8; kk++) { float t = xr[kk*32 + lane]; s += t; s2 += t*t; }
        #pragma unroll
        for (int off = 16; off; off >>= 1) {
            s  += __shfl_xor_sync(0xffffffffu, s,  off);
            s2 += __shfl_xor_sync(0xffffffffu, s2, off);
        }
        if (lane == 0) {
            float mu = s * (1.f/256.f);
            smu[r] = mu;
            srstd[r] = rsqrtf(s2 * (1.f/256.f) - mu*mu + 1e-5f);
        }
    }
    __syncthreads();

    int tx = tid & 15, ty = tid >> 4;
    u64 acc[8][4] = {};

    for (int kc = 0; kc < 16; kc++) {
        __syncthreads();
        // fill aS: 128 rows x 16 k
        #pragma unroll
        for (int q = 0; q < 8; q++) {
            int lin = q*256 + tid;
            int r = lin >> 4, kk = lin & 15;
            int k = kc*16 + kk;
            float v = x[(size_t)(m0 + r) * Dn + k];
            v = (v - smu[r]) * srstd[r] * sg[k] + sbe[k];
            aS[kk][r] = pk2(v, v);
        }
        // fill wS: 16 k x 128 cols (float4)
        #pragma unroll
        for (int q = 0; q < 2; q++) {
            int idx = q*256 + tid;
            int kk = idx >> 5, g = idx & 31;
            *(float4*)&wS[kk][g*4] =
                *(const float4*)&w_in[(size_t)(kc*16 + kk) * 512 + n0 + g*4];
        }
        __syncthreads();
        #pragma unroll
        for (int k = 0; k < 16; k++) {
            u64 h[8];
            #pragma unroll
            for (int i = 0; i < 8; i++) h[i] = aS[k][ty*8 + i];
            u64 w4[4];
            #pragma unroll
            for (int q = 0; q < 4; q++) w4[q] = *(const u64*)&wS[k][q*32 + tx*2];
            #pragma unroll
            for (int i = 0; i < 8; i++)
                #pragma unroll
                for (int q = 0; q < 4; q++)
                    acc[i][q] = ffma2(h[i], w4[q], acc[i][q]);
        }
    }

    bool isGate = (n0 >= 256);
    #pragma unroll
    for (int i = 0; i < 8; i++) {
        int row = m0 + ty*8 + i;
        #pragma unroll
        for (int q = 0; q < 4; q++) {
            int n = n0 + q*32 + tx*2;
            float lo, hi; upk2(acc[i][q], lo, hi);
            float v0 = lo + b_in[n];
            float v1 = hi + b_in[n+1];
            if (isGate) {
                g_gate[(size_t)row * Dn + (n   - 256)] = sigmoidf_(v0);
                g_gate[(size_t)row * Dn + (n+1 - 256)] = sigmoidf_(v1);
            } else {
                g_xin[(size_t)row * Dn + n  ] = v0;
                g_xin[(size_t)row * Dn + n+1] = v1;
            }
        }
    }
}

// =============== K2: depthwise 3x3 conv (SAME) + SiLU ========================
__global__ __launch_bounds__(256) void k_conv(
    const float* __restrict__ conv_w, const float* __restrict__ conv_b)
{
    int c = threadIdx.x;
    int b = blockIdx.x / Hn, h = blockIdx.x % Hn;

    float kw[3][3];
    #pragma unroll
    for (int dh = 0; dh < 3; dh++)
        #pragma unroll
        for (int dw = 0; dw < 3; dw++)
            kw[dh][dw] = conv_w[(dh*3 + dw) * Dn + c];
    float bias = conv_b[c];

    const float* rp[3]; bool hv[3];
    #pragma unroll
    for (int dh = 0; dh < 3; dh++) {
        int hh = h + dh - 1;
        hv[dh] = (hh >= 0 && hh < Hn);
        rp[dh] = g_xin + ((size_t)(b*Hn + (hv[dh] ? hh : 0)) * Wn) * Dn + c;
    }

    float v[3][3];
    #pragma unroll
    for (int dh = 0; dh < 3; dh++) {
        v[dh][0] = 0.f;
        v[dh][1] = hv[dh] ? rp[dh][0]   : 0.f;
        v[dh][2] = hv[dh] ? rp[dh][Dn]  : 0.f;
    }

    float* up = g_u + ((size_t)(b*Hn + h) * Wn) * Dn + c;
    for (int w = 0; w < Wn; w++) {
        float s = bias;
        #pragma unroll
        for (int dh = 0; dh < 3; dh++)
            #pragma unroll
            for (int dw = 0; dw < 3; dw++)
                s += v[dh][dw] * kw[dh][dw];
        up[(size_t)w * Dn] = s * sigmoidf_(s);
        #pragma unroll
        for (int dh = 0; dh < 3; dh++) {
            v[dh][0] = v[dh][1]; v[dh][1] = v[dh][2];
            int wn = w + 2;
            v[dh][2] = (hv[dh] && wn < Wn) ? rp[dh][(size_t)wn * Dn] : 0.f;
        }
    }
}

// =============== K3a: per-chunk fwd local final + Total =======================
__global__ __launch_bounds__(256) void k_scanA(
    const float* __restrict__ a_logit, const float* __restrict__ ssm_b)
{
    int c = threadIdx.x;
    int j = blockIdx.x, b = blockIdx.y, o = blockIdx.z;
    float a = fminf(fmaxf(sigmoidf_(a_logit[c]), 1e-4f), 1.f - 1e-4f);
    float bb = ssm_b[c];

    size_t base, stride;
    if (o == 0) { base = ((size_t)(b*Hn + j) * Wn) * Dn + c;      stride = Dn; }
    else        { base = ((size_t)b*Hn*Wn + (size_t)j) * Dn + c;  stride = (size_t)Wn * Dn; }

    float lf = 0.f, P = 0.f, ap = 1.f;
    for (int g = 0; g < 12; g++) {
        float t[8];
        #pragma unroll
        for (int i = 0; i < 8; i++) t[i] = g_u[base + (size_t)(g*8 + i) * stride];
        #pragma unroll
        for (int i = 0; i < 8; i++) {
            float bu = bb * t[i];
            lf = a * lf + bu;
            P += ap * bu;
            ap *= a;
        }
    }
    g_fin[o][0][b][j][c] = lf;
    g_fin[o][1][b][j][c] = P;
}

// =============== K3b: chunk-level carry scans (prefetched) ====================
__global__ __launch_bounds__(256) void k_scanB(const float* __restrict__ a_logit)
{
    int c = threadIdx.x;
    int b = blockIdx.x, o = blockIdx.y;
    float a = fminf(fmaxf(sigmoidf_(a_logit[c]), 1e-4f), 1.f - 1e-4f);
    float a96 = (float)exp(96.0 * log((double)a));

    float carry = 0.f;
    for (int g = 0; g < 8; g++) {
        float t[12];
        #pragma unroll
        for (int i = 0; i < 12; i++) t[i] = g_fin[o][0][b][g*12 + i][c];
        #pragma unroll
        for (int i = 0; i < 12; i++) {
            g_carry[o][0][b][g*12 + i][c] = carry;
            carry = a96 * carry + t[i];
        }
    }
    carry = 0.f;
    for (int g = 7; g >= 0; g--) {
        float t[12];
        #pragma unroll
        for (int i = 0; i < 12; i++) t[i] = g_fin[o][1][b][g*12 + i][c];
        #pragma unroll
        for (int i = 11; i >= 0; i--) {
            g_carry[o][1][b][g*12 + i][c] = carry;
            carry = a96 * carry + t[i];
        }
    }
}

// =============== K3c: apply pass ==============================================
__global__ __launch_bounds__(256) void k_scanC(
    const float* __restrict__ a_logit, const float* __restrict__ ssm_b,
    const float* __restrict__ ssm_c,  const float* __restrict__ ssm_d, int o)
{
    int c = threadIdx.x;
    int j = blockIdx.x, b = blockIdx.y;
    float a = fminf(fmaxf(sigmoidf_(a_logit[c]), 1e-4f), 1.f - 1e-4f);
    float inva = 1.f / a;
    float a96 = (float)exp(96.0 * log((double)a));
    float bb = ssm_b[c], cc = ssm_c[c], dd = ssm_d[c];

    float sf = g_carry[o][0][b][j][c];
    float cb96 = a96 * g_carry[o][1][b][j][c];
    float Total = g_fin[o][1][b][j][c];

    size_t base, stride;
    if (o == 0) { base = ((size_t)(b*Hn + j) * Wn) * Dn + c;      stride = Dn; }
    else        { base = ((size_t)b*Hn*Wn + (size_t)j) * Dn + c;  stride = (size_t)Wn * Dn; }

    float P = 0.f, ap = 1.f, rap = 1.f;
    for (int g = 0; g < 12; g++) {
        float t[8], yv[8];
        #pragma unroll
        for (int i = 0; i < 8; i++) t[i] = g_u[base + (size_t)(g*8 + i) * stride];
        if (o == 1) {
            #pragma unroll
            for (int i = 0; i < 8; i++) yv[i] = g_y[base + (size_t)(g*8 + i) * stride];
        }
        #pragma unroll
        for (int i = 0; i < 8; i++) {
            size_t addr = base + (size_t)(g*8 + i) * stride;
            float ux = t[i];
            sf = a * sf + bb * ux;
            float sb = (Total - P + cb96) * rap;
            float contrib = 0.25f * cc * (sf + sb);
            if (o == 0) g_y[addr] = contrib + dd * ux;
            else        g_y[addr] = yv[i] + contrib;
            P += ap * bb * ux;
            ap *= a; rap *= inva;
        }
    }
}

// =============== K4: gate*y -> out_proj GEMM + bias + residual ================
// grid: (2 nblk, 576 mblk), 256 thr. FFMA2, same tiling as K1.
__global__ __launch_bounds__(256) void k_outproj(
    const float* __restrict__ x, const float* __restrict__ w_out,
    const float* __restrict__ b_out, float* __restrict__ out)
{
    __shared__ u64   aS[16][130];
    __shared__ float wS[16][132];
    int tid = threadIdx.x;
    int n0 = blockIdx.x * 128, m0 = blockIdx.y * 128;
    int tx = tid & 15, ty = tid >> 4;
    u64 acc[8][4] = {};

    for (int kc = 0; kc < 16; kc++) {
        __syncthreads();
        #pragma unroll
        for (int q = 0; q < 8; q++) {
            int lin = q*256 + tid;
            int r = lin >> 4, kk = lin & 15;
            size_t idx = (size_t)(m0 + r) * Dn + kc*16 + kk;
            float v = g_y[idx] * g_gate[idx];
            aS[kk][r] = pk2(v, v);
        }
        #pragma unroll
        for (int q = 0; q < 2; q++) {
            int idx = q*256 + tid;
            int kk = idx >> 5, g = idx & 31;
            *(float4*)&wS[kk][g*4] =
                *(const float4*)&w_out[(size_t)(kc*16 + kk) * Dn + n0 + g*4];
        }
        __syncthreads();
        #pragma unroll
        for (int k = 0; k < 16; k++) {
            u64 h[8];
            #pragma unroll
            for (int i = 0; i < 8; i++) h[i] = aS[k][ty*8 + i];
            u64 w4[4];
            #pragma unroll
            for (int q = 0; q < 4; q++) w4[q] = *(const u64*)&wS[k][q*32 + tx*2];
            #pragma unroll
            for (int i = 0; i < 8; i++)
                #pragma unroll
                for (int q = 0; q < 4; q++)
                    acc[i][q] = ffma2(h[i], w4[q], acc[i][q]);
        }
    }

    #pragma unroll
    for (int i = 0; i < 8; i++) {
        int row = m0 + ty*8 + i;
        #pragma unroll
        for (int q = 0; q < 4; q++) {
            int n = n0 + q*32 + tx*2;
            float lo, hi; upk2(acc[i][q], lo, hi);
            out[(size_t)row * Dn + n  ] = lo + b_out[n]   + x[(size_t)row * Dn + n];
            out[(size_t)row * Dn + n+1] = hi + b_out[n+1] + x[(size_t)row * Dn + n+1];
        }
    }
}

// ==============================================================================
extern "C" void kernel_launch(void* const* d_in, const int* in_sizes, int n_in,
                              void* d_out, int out_size)
{
    const float* x       = (const float*)d_in[0];
    const float* ln_g    = (const float*)d_in[1];
    const float* ln_b    = (const float*)d_in[2];
    const float* w_in    = (const float*)d_in[3];
    const float* b_in    = (const float*)d_in[4];
    const float* conv_w  = (const float*)d_in[5];
    const float* conv_b  = (const float*)d_in[6];
    const float* a_logit = (const float*)d_in[7];
    const float* ssm_b   = (const float*)d_in[8];
    const float* ssm_c   = (const float*)d_in[9];
    const float* ssm_d   = (const float*)d_in[10];
    const float* w_out   = (const float*)d_in[11];
    const float* b_out   = (const float*)d_in[12];
    float* out = (float*)d_out;

    k_ln_inproj<<<dim3(4, NPIX/128), 256>>>(x, ln_g, ln_b, w_in, b_in);
    k_conv<<<Bn*Hn, 256>>>(conv_w, conv_b);
    k_scanA<<<dim3(NCH, Bn, 2), 256>>>(a_logit, ssm_b);
    k_scanB<<<dim3(Bn, 2), 256>>>(a_logit);
    k_scanC<<<dim3(NCH, Bn), 256>>>(a_logit, ssm_b, ssm_c, ssm_d, 0);
    k_scanC<<<dim3(NCH, Bn), 256>>>(a_logit, ssm_b, ssm_c, ssm_d, 1);
    k_outproj<<<dim3(2, NPIX/128), 256>>>(x, w_out, b_out, out);
}

// round 4
// speedup vs baseline: 2.5411x; 1.8957x over previous
#include <cuda_runtime.h>
#include <cuda_bf16.h>
#include <math.h>
#include <stdint.h>

#define Bn 8
#define Hn 96
#define Wn 96
#define Dn 256
#define NPIX (Bn*Hn*Wn)          // 73728
#define NCH 96

typedef unsigned long long u64;
typedef __nv_bfloat16 bf16;

// ---------------- scratch (device globals) ------------------------------------
__device__ float g_xin[NPIX*Dn];
__device__ float g_gate[NPIX*Dn];
__device__ float g_u[NPIX*Dn];
__device__ float g_y[NPIX*Dn];
__device__ float g_fin[2][2][Bn][NCH][Dn];
__device__ float g_carry[2][2][Bn][NCH][Dn];
// bf16 split operands
__device__ bf16 g_ahi[NPIX*Dn];
__device__ bf16 g_alo[NPIX*Dn];
__device__ bf16 g_wiT_hi[512*256], g_wiT_lo[512*256];   // w_in^T [n][k]
__device__ bf16 g_woT_hi[256*256], g_woT_lo[256*256];   // w_out^T [n][k]

__device__ __forceinline__ float sigmoidf_(float v){ return 1.f/(1.f+expf(-v)); }

__device__ __forceinline__ uint32_t smem_u32(const void* p){
    uint32_t a;
    asm("{ .reg .u64 t; cvta.to.shared.u64 t, %1; cvt.u32.u64 %0, t; }" : "=r"(a) : "l"(p));
    return a;
}
__device__ __forceinline__ void cp16(uint32_t sdst, const void* gsrc){
    asm volatile("cp.async.cg.shared.global [%0], [%1], 16;" :: "r"(sdst), "l"(gsrc));
}
__device__ __forceinline__ void ldsm4(uint32_t* r, uint32_t a){
    asm volatile("ldmatrix.sync.aligned.m8n8.x4.shared.b16 {%0,%1,%2,%3}, [%4];"
        : "=r"(r[0]),"=r"(r[1]),"=r"(r[2]),"=r"(r[3]) : "r"(a));
}
__device__ __forceinline__ void mma16816(float* d, const uint32_t* a, const uint32_t* b){
    asm volatile("mma.sync.aligned.m16n8k16.row.col.f32.bf16.bf16.f32 "
        "{%0,%1,%2,%3}, {%4,%5,%6,%7}, {%8,%9}, {%0,%1,%2,%3};"
        : "+f"(d[0]), "+f"(d[1]), "+f"(d[2]), "+f"(d[3])
        : "r"(a[0]), "r"(a[1]), "r"(a[2]), "r"(a[3]), "r"(b[0]), "r"(b[1]));
}

// =============== prep: transpose + split weights ==============================
__global__ __launch_bounds__(256) void k_wsplit(
    const float* __restrict__ w_in, const float* __restrict__ w_out)
{
    int k = threadIdx.x;
    int n = blockIdx.x;
    if (n < 512) {
        float v = w_in[(size_t)k * 512 + n];
        bf16 h = __float2bfloat16(v);
        g_wiT_hi[(size_t)n*256 + k] = h;
        g_wiT_lo[(size_t)n*256 + k] = __float2bfloat16(v - __bfloat162float(h));
    } else {
        int nn = n - 512;
        float v = w_out[(size_t)k * 256 + nn];
        bf16 h = __float2bfloat16(v);
        g_woT_hi[(size_t)nn*256 + k] = h;
        g_woT_lo[(size_t)nn*256 + k] = __float2bfloat16(v - __bfloat162float(h));
    }
}

// =============== prep: LayerNorm -> bf16 hi/lo split ==========================
__global__ __launch_bounds__(256) void k_ln_split(
    const float* __restrict__ x, const float* __restrict__ ln_g,
    const float* __restrict__ ln_b)
{
    int tid = threadIdx.x, lane = tid & 31, warp = tid >> 5;
    #pragma unroll
    for (int rr = 0; rr < 4; rr++) {
        int row = blockIdx.x * 32 + warp * 4 + rr;
        const float* xr = x + (size_t)row * Dn;
        float4 v0 = *(const float4*)(xr + lane*4);
        float4 v1 = *(const float4*)(xr + 128 + lane*4);
        float s  = v0.x+v0.y+v0.z+v0.w + v1.x+v1.y+v1.z+v1.w;
        float s2 = v0.x*v0.x+v0.y*v0.y+v0.z*v0.z+v0.w*v0.w
                 + v1.x*v1.x+v1.y*v1.y+v1.z*v1.z+v1.w*v1.w;
        #pragma unroll
        for (int off = 16; off; off >>= 1) {
            s  += __shfl_xor_sync(0xffffffffu, s,  off);
            s2 += __shfl_xor_sync(0xffffffffu, s2, off);
        }
        float mu = s * (1.f/256.f);
        float rstd = rsqrtf(s2 * (1.f/256.f) - mu*mu + 1e-5f);
        #pragma unroll
        for (int half = 0; half < 2; half++) {
            int col = half*128 + lane*4;
            float4 v = half ? v1 : v0;
            float4 gg = *(const float4*)(ln_g + col);
            float4 bb = *(const float4*)(ln_b + col);
            float h0 = (v.x - mu)*rstd*gg.x + bb.x;
            float h1 = (v.y - mu)*rstd*gg.y + bb.y;
            float h2 = (v.z - mu)*rstd*gg.z + bb.z;
            float h3 = (v.w - mu)*rstd*gg.w + bb.w;
            bf16 a0=__float2bfloat16(h0), a1=__float2bfloat16(h1);
            bf16 a2=__float2bfloat16(h2), a3=__float2bfloat16(h3);
            uint2 hi_pack, lo_pack;
            hi_pack.x = ((uint32_t)__bfloat16_as_ushort(a1)<<16) | __bfloat16_as_ushort(a0);
            hi_pack.y = ((uint32_t)__bfloat16_as_ushort(a3)<<16) | __bfloat16_as_ushort(a2);
            bf16 l0=__float2bfloat16(h0-__bfloat162float(a0));
            bf16 l1=__float2bfloat16(h1-__bfloat162float(a1));
            bf16 l2=__float2bfloat16(h2-__bfloat162float(a2));
            bf16 l3=__float2bfloat16(h3-__bfloat162float(a3));
            lo_pack.x = ((uint32_t)__bfloat16_as_ushort(l1)<<16) | __bfloat16_as_ushort(l0);
            lo_pack.y = ((uint32_t)__bfloat16_as_ushort(l3)<<16) | __bfloat16_as_ushort(l2);
            *(uint2*)(g_ahi + (size_t)row*Dn + col) = hi_pack;
            *(uint2*)(g_alo + (size_t)row*Dn + col) = lo_pack;
        }
    }
}

// =============== HMMA split-bf16 GEMM =========================================
// tile 128x128, K chunks of 64, double-buffered cp.async, SW128 swizzle.
#define TILE_B 16384           // 128 rows x 128B
#define BUF_B  (4*TILE_B)      // Ah, Al, Bh, Bl
#define SMEM_GEMM (2*BUF_B)    // 131072

__device__ __forceinline__ void load_chunk(
    uint32_t sbuf, const bf16* __restrict__ Ah, const bf16* __restrict__ Al,
    const bf16* __restrict__ Bh, const bf16* __restrict__ Bl,
    int m0, int n0, int kc, int tid)
{
    #pragma unroll
    for (int t = 0; t < 4; t++) {
        const bf16* src = (t==0)?Ah:(t==1)?Al:(t==2)?Bh:Bl;
        int r0 = (t < 2) ? m0 : n0;
        #pragma unroll
        for (int q = 0; q < 4; q++) {
            int u = q*256 + tid;
            int r = u >> 3, g = u & 7;
            uint32_t boff = r*128 + g*16;
            uint32_t swo = boff ^ ((boff>>3)&0x70);
            cp16(sbuf + t*TILE_B + swo, src + (size_t)(r0 + r)*Dn + kc + g*8);
        }
    }
}

__device__ __forceinline__ void compute_chunk(
    uint32_t sbuf, float acc[4][4][4], int wm, int wn, int lane)
{
    uint32_t aAh = sbuf, aAl = sbuf + TILE_B;
    uint32_t aBh = sbuf + 2*TILE_B, aBl = sbuf + 3*TILE_B;
    int arow = wm + (lane&7) + 8*((lane>>3)&1);
    int akb0 = 16*(lane>>4);
    int brow = wn + 8*(lane>>4) + (lane&7);
    int bkb0 = 16*((lane>>3)&1);
    #pragma unroll
    for (int ks = 0; ks < 4; ks++) {
        int kb = ks*32;
        uint32_t ah[4][4], al[4][4], bh[4][2], bl[4][2];
        #pragma unroll
        for (int mt = 0; mt < 4; mt++) {
            uint32_t boff = (uint32_t)(arow + mt*16)*128 + kb + akb0;
            uint32_t swo = boff ^ ((boff>>3)&0x70);
            ldsm4(ah[mt], aAh + swo);
            ldsm4(al[mt], aAl + swo);
        }
        #pragma unroll
        for (int p = 0; p < 2; p++) {
            uint32_t boff = (uint32_t)(brow + p*16)*128 + kb + bkb0;
            uint32_t swo = boff ^ ((boff>>3)&0x70);
            uint32_t t[4];
            ldsm4(t, aBh + swo);
            bh[p*2][0]=t[0]; bh[p*2][1]=t[1]; bh[p*2+1][0]=t[2]; bh[p*2+1][1]=t[3];
            ldsm4(t, aBl + swo);
            bl[p*2][0]=t[0]; bl[p*2][1]=t[1]; bl[p*2+1][0]=t[2]; bl[p*2+1][1]=t[3];
        }
        #pragma unroll
        for (int mt = 0; mt < 4; mt++)
            #pragma unroll
            for (int nt = 0; nt < 4; nt++) {
                mma16816(acc[mt][nt], ah[mt], bh[nt]);
                mma16816(acc[mt][nt], ah[mt], bl[nt]);
                mma16816(acc[mt][nt], al[mt], bh[nt]);
            }
    }
}

__global__ __launch_bounds__(256, 1) void k_gemm(
    int mode, const float* __restrict__ bias,
    const float* __restrict__ xres, float* __restrict__ outp)
{
    extern __shared__ char smem[];
    uint32_t sb = smem_u32(smem);
    int tid = threadIdx.x, lane = tid & 31, wid = tid >> 5;
    int n0 = blockIdx.x * 128, m0 = blockIdx.y * 128;
    int wm = (wid & 1) * 64, wn = (wid >> 1) * 32;
    const bf16* Bh = mode ? g_woT_hi : g_wiT_hi;
    const bf16* Bl = mode ? g_woT_lo : g_wiT_lo;
    uint32_t buf0 = sb, buf1 = sb + BUF_B;
    float acc[4][4][4] = {};

    load_chunk(buf0, g_ahi, g_alo, Bh, Bl, m0, n0, 0, tid);
    asm volatile("cp.async.commit_group;" ::: "memory");
    load_chunk(buf1, g_ahi, g_alo, Bh, Bl, m0, n0, 64, tid);
    asm volatile("cp.async.commit_group;" ::: "memory");

    asm volatile("cp.async.wait_group 1;" ::: "memory");
    __syncthreads();
    compute_chunk(buf0, acc, wm, wn, lane);
    __syncthreads();
    load_chunk(buf0, g_ahi, g_alo, Bh, Bl, m0, n0, 128, tid);
    asm volatile("cp.async.commit_group;" ::: "memory");

    asm volatile("cp.async.wait_group 1;" ::: "memory");
    __syncthreads();
    compute_chunk(buf1, acc, wm, wn, lane);
    __syncthreads();
    load_chunk(buf1, g_ahi, g_alo, Bh, Bl, m0, n0, 192, tid);
    asm volatile("cp.async.commit_group;" ::: "memory");

    asm volatile("cp.async.wait_group 1;" ::: "memory");
    __syncthreads();
    compute_chunk(buf0, acc, wm, wn, lane);

    asm volatile("cp.async.wait_group 0;" ::: "memory");
    __syncthreads();
    compute_chunk(buf1, acc, wm, wn, lane);

    // epilogue
    #pragma unroll
    for (int mt = 0; mt < 4; mt++) {
        int r0 = m0 + wm + mt*16 + (lane >> 2);
        #pragma unroll
        for (int nt = 0; nt < 4; nt++) {
            int col = n0 + wn + nt*8 + (lane & 3)*2;
            float2 bv = *(const float2*)(bias + col);
            float v0 = acc[mt][nt][0] + bv.x, v1 = acc[mt][nt][1] + bv.y;
            float v2 = acc[mt][nt][2] + bv.x, v3 = acc[mt][nt][3] + bv.y;
            if (mode == 0) {
                if (col >= 256) {
                    float2 o0 = {sigmoidf_(v0), sigmoidf_(v1)};
                    float2 o1 = {sigmoidf_(v2), sigmoidf_(v3)};
                    *(float2*)(g_gate + (size_t)r0*Dn + col - 256) = o0;
                    *(float2*)(g_gate + (size_t)(r0+8)*Dn + col - 256) = o1;
                } else {
                    float2 o0 = {v0, v1}, o1 = {v2, v3};
                    *(float2*)(g_xin + (size_t)r0*Dn + col) = o0;
                    *(float2*)(g_xin + (size_t)(r0+8)*Dn + col) = o1;
                }
            } else {
                float2 x0 = *(const float2*)(xres + (size_t)r0*Dn + col);
                float2 x1 = *(const float2*)(xres + (size_t)(r0+8)*Dn + col);
                float2 o0 = {v0 + x0.x, v1 + x0.y};
                float2 o1 = {v2 + x1.x, v3 + x1.y};
                *(float2*)(outp + (size_t)r0*Dn + col) = o0;
                *(float2*)(outp + (size_t)(r0+8)*Dn + col) = o1;
            }
        }
    }
}

// =============== K2: depthwise 3x3 conv (SAME) + SiLU ========================
__global__ __launch_bounds__(256) void k_conv(
    const float* __restrict__ conv_w, const float* __restrict__ conv_b)
{
    int c = threadIdx.x;
    int b = blockIdx.x / Hn, h = blockIdx.x % Hn;

    float kw[3][3];
    #pragma unroll
    for (int dh = 0; dh < 3; dh++)
        #pragma unroll
        for (int dw = 0; dw < 3; dw++)
            kw[dh][dw] = conv_w[(dh*3 + dw) * Dn + c];
    float bias = conv_b[c];

    const float* rp[3]; bool hv[3];
    #pragma unroll
    for (int dh = 0; dh < 3; dh++) {
        int hh = h + dh - 1;
        hv[dh] = (hh >= 0 && hh < Hn);
        rp[dh] = g_xin + ((size_t)(b*Hn + (hv[dh] ? hh : 0)) * Wn) * Dn + c;
    }

    float v[3][3];
    #pragma unroll
    for (int dh = 0; dh < 3; dh++) {
        v[dh][0] = 0.f;
        v[dh][1] = hv[dh] ? rp[dh][0]   : 0.f;
        v[dh][2] = hv[dh] ? rp[dh][Dn]  : 0.f;
    }

    float* up = g_u + ((size_t)(b*Hn + h) * Wn) * Dn + c;
    for (int w = 0; w < Wn; w++) {
        float s = bias;
        #pragma unroll
        for (int dh = 0; dh < 3; dh++)
            #pragma unroll
            for (int dw = 0; dw < 3; dw++)
                s += v[dh][dw] * kw[dh][dw];
        up[(size_t)w * Dn] = s * sigmoidf_(s);
        #pragma unroll
        for (int dh = 0; dh < 3; dh++) {
            v[dh][0] = v[dh][1]; v[dh][1] = v[dh][2];
            int wn = w + 2;
            v[dh][2] = (hv[dh] && wn < Wn) ? rp[dh][(size_t)wn * Dn] : 0.f;
        }
    }
}

// =============== K3a: per-chunk fwd local final + Total =======================
__global__ __launch_bounds__(256) void k_scanA(
    const float* __restrict__ a_logit, const float* __restrict__ ssm_b)
{
    int c = threadIdx.x;
    int j = blockIdx.x, b = blockIdx.y, o = blockIdx.z;
    float a = fminf(fmaxf(sigmoidf_(a_logit[c]), 1e-4f), 1.f - 1e-4f);
    float bb = ssm_b[c];

    size_t base, stride;
    if (o == 0) { base = ((size_t)(b*Hn + j) * Wn) * Dn + c;      stride = Dn; }
    else        { base = ((size_t)b*Hn*Wn + (size_t)j) * Dn + c;  stride = (size_t)Wn * Dn; }

    float lf = 0.f, P = 0.f, ap = 1.f;
    for (int g = 0; g < 12; g++) {
        float t[8];
        #pragma unroll
        for (int i = 0; i < 8; i++) t[i] = g_u[base + (size_t)(g*8 + i) * stride];
        #pragma unroll
        for (int i = 0; i < 8; i++) {
            float bu = bb * t[i];
            lf = a * lf + bu;
            P += ap * bu;
            ap *= a;
        }
    }
    g_fin[o][0][b][j][c] = lf;
    g_fin[o][1][b][j][c] = P;
}

// =============== K3b: chunk-level carry scans =================================
__global__ __launch_bounds__(256) void k_scanB(const float* __restrict__ a_logit)
{
    int c = threadIdx.x;
    int b = blockIdx.x, o = blockIdx.y;
    float a = fminf(fmaxf(sigmoidf_(a_logit[c]), 1e-4f), 1.f - 1e-4f);
    float a96 = (float)exp(96.0 * log((double)a));

    float carry = 0.f;
    for (int g = 0; g < 8; g++) {
        float t[12];
        #pragma unroll
        for (int i = 0; i < 12; i++) t[i] = g_fin[o][0][b][g*12 + i][c];
        #pragma unroll
        for (int i = 0; i < 12; i++) {
            g_carry[o][0][b][g*12 + i][c] = carry;
            carry = a96 * carry + t[i];
        }
    }
    carry = 0.f;
    for (int g = 7; g >= 0; g--) {
        float t[12];
        #pragma unroll
        for (int i = 0; i < 12; i++) t[i] = g_fin[o][1][b][g*12 + i][c];
        #pragma unroll
        for (int i = 11; i >= 0; i--) {
            g_carry[o][1][b][g*12 + i][c] = carry;
            carry = a96 * carry + t[i];
        }
    }
}

// =============== K3c: apply pass; o==1 fuses gate-mult + bf16 split ==========
__global__ __launch_bounds__(256) void k_scanC(
    const float* __restrict__ a_logit, const float* __restrict__ ssm_b,
    const float* __restrict__ ssm_c,  const float* __restrict__ ssm_d, int o)
{
    int c = threadIdx.x;
    int j = blockIdx.x, b = blockIdx.y;
    float a = fminf(fmaxf(sigmoidf_(a_logit[c]), 1e-4f), 1.f - 1e-4f);
    float inva = 1.f / a;
    float a96 = (float)exp(96.0 * log((double)a));
    float bb = ssm_b[c], cc = ssm_c[c], dd = ssm_d[c];

    float sf = g_carry[o][0][b][j][c];
    float cb96 = a96 * g_carry[o][1][b][j][c];
    float Total = g_fin[o][1][b][j][c];

    size_t base, stride;
    if (o == 0) { base = ((size_t)(b*Hn + j) * Wn) * Dn + c;      stride = Dn; }
    else        { base = ((size_t)b*Hn*Wn + (size_t)j) * Dn + c;  stride = (size_t)Wn * Dn; }

    float P = 0.f, ap = 1.f, rap = 1.f;
    for (int g = 0; g < 12; g++) {
        float t[8], yv[8], gv[8];
        #pragma unroll
        for (int i = 0; i < 8; i++) t[i] = g_u[base + (size_t)(g*8 + i) * stride];
        if (o == 1) {
            #pragma unroll
            for (int i = 0; i < 8; i++) yv[i] = g_y[base + (size_t)(g*8 + i) * stride];
            #pragma unroll
            for (int i = 0; i < 8; i++) gv[i] = g_gate[base + (size_t)(g*8 + i) * stride];
        }
        #pragma unroll
        for (int i = 0; i < 8; i++) {
            size_t addr = base + (size_t)(g*8 + i) * stride;
            float ux = t[i];
            sf = a * sf + bb * ux;
            float sb = (Total - P + cb96) * rap;
            float contrib = 0.25f * cc * (sf + sb);
            if (o == 0) {
                g_y[addr] = contrib + dd * ux;
            } else {
                float fv = (yv[i] + contrib) * gv[i];
                bf16 hbf = __float2bfloat16(fv);
                g_ahi[addr] = hbf;
                g_alo[addr] = __float2bfloat16(fv - __bfloat162float(hbf));
            }
            P += ap * bb * ux;
            ap *= a; rap *= inva;
        }
    }
}

// ==============================================================================
extern "C" void kernel_launch(void* const* d_in, const int* in_sizes, int n_in,
                              void* d_out, int out_size)
{
    const float* x       = (const float*)d_in[0];
    const float* ln_g    = (const float*)d_in[1];
    const float* ln_b    = (const float*)d_in[2];
    const float* w_in    = (const float*)d_in[3];
    const float* b_in    = (const float*)d_in[4];
    const float* conv_w  = (const float*)d_in[5];
    const float* conv_b  = (const float*)d_in[6];
    const float* a_logit = (const float*)d_in[7];
    const float* ssm_b   = (const float*)d_in[8];
    const float* ssm_c   = (const float*)d_in[9];
    const float* ssm_d   = (const float*)d_in[10];
    const float* w_out   = (const float*)d_in[11];
    const float* b_out   = (const float*)d_in[12];
    float* out = (float*)d_out;

    cudaFuncSetAttribute(k_gemm, cudaFuncAttributeMaxDynamicSharedMemorySize, SMEM_GEMM);

    k_wsplit<<<768, 256>>>(w_in, w_out);
    k_ln_split<<<NPIX/32, 256>>>(x, ln_g, ln_b);
    k_gemm<<<dim3(4, NPIX/128), 256, SMEM_GEMM>>>(0, b_in, nullptr, nullptr);
    k_conv<<<Bn*Hn, 256>>>(conv_w, conv_b);
    k_scanA<<<dim3(NCH, Bn, 2), 256>>>(a_logit, ssm_b);
    k_scanB<<<dim3(Bn, 2), 256>>>(a_logit);
    k_scanC<<<dim3(NCH, Bn), 256>>>(a_logit, ssm_b, ssm_c, ssm_d, 0);
    k_scanC<<<dim3(NCH, Bn), 256>>>(a_logit, ssm_b, ssm_c, ssm_d, 1);
    k_gemm<<<dim3(2, NPIX/128), 256, SMEM_GEMM>>>(1, b_out, x, out);
}

// round 5
// speedup vs baseline: 2.6929x; 1.0597x over previous
#include <cuda_runtime.h>
#include <cuda_bf16.h>
#include <math.h>
#include <stdint.h>

#define Bn 8
#define Hn 96
#define Wn 96
#define Dn 256
#define NPIX (Bn*Hn*Wn)          // 73728
#define NCH 96

typedef unsigned long long u64;
typedef __nv_bfloat16 bf16;

// ---------------- scratch (device globals) ------------------------------------
__device__ float g_xin[NPIX*Dn];
__device__ float g_gate[NPIX*Dn];
__device__ float g_u[NPIX*Dn];
__device__ float g_y[NPIX*Dn];
__device__ float g_fin[2][2][Bn][NCH][Dn];
__device__ float g_carry[2][2][Bn][NCH][Dn];
// bf16 split operands
__device__ bf16 g_ahi[NPIX*Dn];
__device__ bf16 g_alo[NPIX*Dn];
__device__ bf16 g_wiT_hi[512*256], g_wiT_lo[512*256];   // w_in^T [n][k]
__device__ bf16 g_woT_hi[256*256], g_woT_lo[256*256];   // w_out^T [n][k]

__device__ __forceinline__ float sigmoidf_(float v){ return 1.f/(1.f+expf(-v)); }

__device__ __forceinline__ uint32_t smem_u32(const void* p){
    uint32_t a;
    asm("{ .reg .u64 t; cvta.to.shared.u64 t, %1; cvt.u32.u64 %0, t; }" : "=r"(a) : "l"(p));
    return a;
}
__device__ __forceinline__ void cp16(uint32_t sdst, const void* gsrc){
    asm volatile("cp.async.cg.shared.global [%0], [%1], 16;" :: "r"(sdst), "l"(gsrc));
}
__device__ __forceinline__ void ldsm4(uint32_t* r, uint32_t a){
    asm volatile("ldmatrix.sync.aligned.m8n8.x4.shared.b16 {%0,%1,%2,%3}, [%4];"
        : "=r"(r[0]),"=r"(r[1]),"=r"(r[2]),"=r"(r[3]) : "r"(a));
}
__device__ __forceinline__ void mma16816(float* d, const uint32_t* a, const uint32_t* b){
    asm volatile("mma.sync.aligned.m16n8k16.row.col.f32.bf16.bf16.f32 "
        "{%0,%1,%2,%3}, {%4,%5,%6,%7}, {%8,%9}, {%0,%1,%2,%3};"
        : "+f"(d[0]), "+f"(d[1]), "+f"(d[2]), "+f"(d[3])
        : "r"(a[0]), "r"(a[1]), "r"(a[2]), "r"(a[3]), "r"(b[0]), "r"(b[1]));
}

// =============== prep: transpose + split weights ==============================
__global__ __launch_bounds__(256) void k_wsplit(
    const float* __restrict__ w_in, const float* __restrict__ w_out)
{
    int k = threadIdx.x;
    int n = blockIdx.x;
    if (n < 512) {
        float v = w_in[(size_t)k * 512 + n];
        bf16 h = __float2bfloat16(v);
        g_wiT_hi[(size_t)n*256 + k] = h;
        g_wiT_lo[(size_t)n*256 + k] = __float2bfloat16(v - __bfloat162float(h));
    } else {
        int nn = n - 512;
        float v = w_out[(size_t)k * 256 + nn];
        bf16 h = __float2bfloat16(v);
        g_woT_hi[(size_t)nn*256 + k] = h;
        g_woT_lo[(size_t)nn*256 + k] = __float2bfloat16(v - __bfloat162float(h));
    }
}

// =============== prep: LayerNorm -> bf16 hi/lo split ==========================
__global__ __launch_bounds__(256) void k_ln_split(
    const float* __restrict__ x, const float* __restrict__ ln_g,
    const float* __restrict__ ln_b)
{
    int tid = threadIdx.x, lane = tid & 31, warp = tid >> 5;
    #pragma unroll
    for (int rr = 0; rr < 4; rr++) {
        int row = blockIdx.x * 32 + warp * 4 + rr;
        const float* xr = x + (size_t)row * Dn;
        float4 v0 = *(const float4*)(xr + lane*4);
        float4 v1 = *(const float4*)(xr + 128 + lane*4);
        float s  = v0.x+v0.y+v0.z+v0.w + v1.x+v1.y+v1.z+v1.w;
        float s2 = v0.x*v0.x+v0.y*v0.y+v0.z*v0.z+v0.w*v0.w
                 + v1.x*v1.x+v1.y*v1.y+v1.z*v1.z+v1.w*v1.w;
        #pragma unroll
        for (int off = 16; off; off >>= 1) {
            s  += __shfl_xor_sync(0xffffffffu, s,  off);
            s2 += __shfl_xor_sync(0xffffffffu, s2, off);
        }
        float mu = s * (1.f/256.f);
        float rstd = rsqrtf(s2 * (1.f/256.f) - mu*mu + 1e-5f);
        #pragma unroll
        for (int half = 0; half < 2; half++) {
            int col = half*128 + lane*4;
            float4 v = half ? v1 : v0;
            float4 gg = *(const float4*)(ln_g + col);
            float4 bb = *(const float4*)(ln_b + col);
            float h0 = (v.x - mu)*rstd*gg.x + bb.x;
            float h1 = (v.y - mu)*rstd*gg.y + bb.y;
            float h2 = (v.z - mu)*rstd*gg.z + bb.z;
            float h3 = (v.w - mu)*rstd*gg.w + bb.w;
            bf16 a0=__float2bfloat16(h0), a1=__float2bfloat16(h1);
            bf16 a2=__float2bfloat16(h2), a3=__float2bfloat16(h3);
            uint2 hi_pack, lo_pack;
            hi_pack.x = ((uint32_t)__bfloat16_as_ushort(a1)<<16) | __bfloat16_as_ushort(a0);
            hi_pack.y = ((uint32_t)__bfloat16_as_ushort(a3)<<16) | __bfloat16_as_ushort(a2);
            bf16 l0=__float2bfloat16(h0-__bfloat162float(a0));
            bf16 l1=__float2bfloat16(h1-__bfloat162float(a1));
            bf16 l2=__float2bfloat16(h2-__bfloat162float(a2));
            bf16 l3=__float2bfloat16(h3-__bfloat162float(a3));
            lo_pack.x = ((uint32_t)__bfloat16_as_ushort(l1)<<16) | __bfloat16_as_ushort(l0);
            lo_pack.y = ((uint32_t)__bfloat16_as_ushort(l3)<<16) | __bfloat16_as_ushort(l2);
            *(uint2*)(g_ahi + (size_t)row*Dn + col) = hi_pack;
            *(uint2*)(g_alo + (size_t)row*Dn + col) = lo_pack;
        }
    }
}

// =============== HMMA split-bf16 GEMM =========================================
#define TILE_B 16384
#define BUF_B  (4*TILE_B)
#define SMEM_GEMM (2*BUF_B)

__device__ __forceinline__ void load_chunk(
    uint32_t sbuf, const bf16* __restrict__ Ah, const bf16* __restrict__ Al,
    const bf16* __restrict__ Bh, const bf16* __restrict__ Bl,
    int m0, int n0, int kc, int tid)
{
    #pragma unroll
    for (int t = 0; t < 4; t++) {
        const bf16* src = (t==0)?Ah:(t==1)?Al:(t==2)?Bh:Bl;
        int r0 = (t < 2) ? m0 : n0;
        #pragma unroll
        for (int q = 0; q < 4; q++) {
            int u = q*256 + tid;
            int r = u >> 3, g = u & 7;
            uint32_t boff = r*128 + g*16;
            uint32_t swo = boff ^ ((boff>>3)&0x70);
            cp16(sbuf + t*TILE_B + swo, src + (size_t)(r0 + r)*Dn + kc + g*8);
        }
    }
}

__device__ __forceinline__ void compute_chunk(
    uint32_t sbuf, float acc[4][4][4], int wm, int wn, int lane)
{
    uint32_t aAh = sbuf, aAl = sbuf + TILE_B;
    uint32_t aBh = sbuf + 2*TILE_B, aBl = sbuf + 3*TILE_B;
    int arow = wm + (lane&7) + 8*((lane>>3)&1);
    int akb0 = 16*(lane>>4);
    int brow = wn + 8*(lane>>4) + (lane&7);
    int bkb0 = 16*((lane>>3)&1);
    #pragma unroll
    for (int ks = 0; ks < 4; ks++) {
        int kb = ks*32;
        uint32_t ah[4][4], al[4][4], bh[4][2], bl[4][2];
        #pragma unroll
        for (int mt = 0; mt < 4; mt++) {
            uint32_t boff = (uint32_t)(arow + mt*16)*128 + kb + akb0;
            uint32_t swo = boff ^ ((boff>>3)&0x70);
            ldsm4(ah[mt], aAh + swo);
            ldsm4(al[mt], aAl + swo);
        }
        #pragma unroll
        for (int p = 0; p < 2; p++) {
            uint32_t boff = (uint32_t)(brow + p*16)*128 + kb + bkb0;
            uint32_t swo = boff ^ ((boff>>3)&0x70);
            uint32_t t[4];
            ldsm4(t, aBh + swo);
            bh[p*2][0]=t[0]; bh[p*2][1]=t[1]; bh[p*2+1][0]=t[2]; bh[p*2+1][1]=t[3];
            ldsm4(t, aBl + swo);
            bl[p*2][0]=t[0]; bl[p*2][1]=t[1]; bl[p*2+1][0]=t[2]; bl[p*2+1][1]=t[3];
        }
        #pragma unroll
        for (int mt = 0; mt < 4; mt++)
            #pragma unroll
            for (int nt = 0; nt < 4; nt++) {
                mma16816(acc[mt][nt], ah[mt], bh[nt]);
                mma16816(acc[mt][nt], ah[mt], bl[nt]);
                mma16816(acc[mt][nt], al[mt], bh[nt]);
            }
    }
}

__global__ __launch_bounds__(256, 1) void k_gemm(
    int mode, const float* __restrict__ bias,
    const float* __restrict__ xres, float* __restrict__ outp)
{
    extern __shared__ char smem[];
    uint32_t sb = smem_u32(smem);
    int tid = threadIdx.x, lane = tid & 31, wid = tid >> 5;
    int n0 = blockIdx.x * 128, m0 = blockIdx.y * 128;
    int wm = (wid & 1) * 64, wn = (wid >> 1) * 32;
    const bf16* Bh = mode ? g_woT_hi : g_wiT_hi;
    const bf16* Bl = mode ? g_woT_lo : g_wiT_lo;
    uint32_t buf0 = sb, buf1 = sb + BUF_B;
    float acc[4][4][4] = {};

    load_chunk(buf0, g_ahi, g_alo, Bh, Bl, m0, n0, 0, tid);
    asm volatile("cp.async.commit_group;" ::: "memory");
    load_chunk(buf1, g_ahi, g_alo, Bh, Bl, m0, n0, 64, tid);
    asm volatile("cp.async.commit_group;" ::: "memory");

    asm volatile("cp.async.wait_group 1;" ::: "memory");
    __syncthreads();
    compute_chunk(buf0, acc, wm, wn, lane);
    __syncthreads();
    load_chunk(buf0, g_ahi, g_alo, Bh, Bl, m0, n0, 128, tid);
    asm volatile("cp.async.commit_group;" ::: "memory");

    asm volatile("cp.async.wait_group 1;" ::: "memory");
    __syncthreads();
    compute_chunk(buf1, acc, wm, wn, lane);
    __syncthreads();
    load_chunk(buf1, g_ahi, g_alo, Bh, Bl, m0, n0, 192, tid);
    asm volatile("cp.async.commit_group;" ::: "memory");

    asm volatile("cp.async.wait_group 1;" ::: "memory");
    __syncthreads();
    compute_chunk(buf0, acc, wm, wn, lane);

    asm volatile("cp.async.wait_group 0;" ::: "memory");
    __syncthreads();
    compute_chunk(buf1, acc, wm, wn, lane);

    #pragma unroll
    for (int mt = 0; mt < 4; mt++) {
        int r0 = m0 + wm + mt*16 + (lane >> 2);
        #pragma unroll
        for (int nt = 0; nt < 4; nt++) {
            int col = n0 + wn + nt*8 + (lane & 3)*2;
            float2 bv = *(const float2*)(bias + col);
            float v0 = acc[mt][nt][0] + bv.x, v1 = acc[mt][nt][1] + bv.y;
            float v2 = acc[mt][nt][2] + bv.x, v3 = acc[mt][nt][3] + bv.y;
            if (mode == 0) {
                if (col >= 256) {
                    float2 o0 = {sigmoidf_(v0), sigmoidf_(v1)};
                    float2 o1 = {sigmoidf_(v2), sigmoidf_(v3)};
                    *(float2*)(g_gate + (size_t)r0*Dn + col - 256) = o0;
                    *(float2*)(g_gate + (size_t)(r0+8)*Dn + col - 256) = o1;
                } else {
                    float2 o0 = {v0, v1}, o1 = {v2, v3};
                    *(float2*)(g_xin + (size_t)r0*Dn + col) = o0;
                    *(float2*)(g_xin + (size_t)(r0+8)*Dn + col) = o1;
                }
            } else {
                float2 x0 = *(const float2*)(xres + (size_t)r0*Dn + col);
                float2 x1 = *(const float2*)(xres + (size_t)(r0+8)*Dn + col);
                float2 o0 = {v0 + x0.x, v1 + x0.y};
                float2 o1 = {v2 + x1.x, v3 + x1.y};
                *(float2*)(outp + (size_t)r0*Dn + col) = o0;
                *(float2*)(outp + (size_t)(r0+8)*Dn + col) = o1;
            }
        }
    }
}

// =============== K2: conv3x3+SiLU fused with ROW-orientation chunk scan ======
// grid B*H=768, 256 thr. w-register-blocked groups of 8 (MLP=24).
__global__ __launch_bounds__(256) void k_conv_rowscan(
    const float* __restrict__ conv_w, const float* __restrict__ conv_b,
    const float* __restrict__ a_logit, const float* __restrict__ ssm_b)
{
    int c = threadIdx.x;
    int b = blockIdx.x / Hn, h = blockIdx.x % Hn;

    float kw[3][3];
    #pragma unroll
    for (int dh = 0; dh < 3; dh++)
        #pragma unroll
        for (int dw = 0; dw < 3; dw++)
            kw[dh][dw] = conv_w[(dh*3 + dw) * Dn + c];
    float bias = conv_b[c];

    const float* rp[3]; float msk[3];
    #pragma unroll
    for (int dh = 0; dh < 3; dh++) {
        int hh = h + dh - 1;
        bool v = (hh >= 0 && hh < Hn);
        msk[dh] = v ? 1.f : 0.f;
        rp[dh] = g_xin + ((size_t)(b*Hn + (v ? hh : 0)) * Wn) * Dn + c;
    }

    float a = fminf(fmaxf(sigmoidf_(a_logit[c]), 1e-4f), 1.f - 1e-4f);
    float bb = ssm_b[c];
    float lf = 0.f, P = 0.f, ap = 1.f;

    float cA[3], cB[3];
    #pragma unroll
    for (int dh = 0; dh < 3; dh++) { cA[dh] = 0.f; cB[dh] = msk[dh] * rp[dh][0]; }

    float* up = g_u + ((size_t)(b*Hn + h) * Wn) * Dn + c;

    for (int g = 0; g < 12; g++) {
        // batched loads: cols 8g+1 .. 8g+8 for 3 rows (24 independent LDGs)
        float nw[3][8];
        #pragma unroll
        for (int i = 0; i < 8; i++) {
            int col = g*8 + 1 + i;
            float cm = (col < Wn) ? 1.f : 0.f;
            int colc = (col < Wn) ? col : (Wn-1);
            #pragma unroll
            for (int dh = 0; dh < 3; dh++)
                nw[dh][i] = cm * msk[dh] * rp[dh][(size_t)colc * Dn];
        }
        float seq[3][10];
        #pragma unroll
        for (int dh = 0; dh < 3; dh++) {
            seq[dh][0] = cA[dh]; seq[dh][1] = cB[dh];
            #pragma unroll
            for (int i = 0; i < 8; i++) seq[dh][2+i] = nw[dh][i];
        }
        #pragma unroll
        for (int i = 0; i < 8; i++) {
            float s = bias;
            #pragma unroll
            for (int dh = 0; dh < 3; dh++) {
                s += kw[dh][0]*seq[dh][i] + kw[dh][1]*seq[dh][i+1] + kw[dh][2]*seq[dh][i+2];
            }
            float u = s * sigmoidf_(s);
            up[(size_t)(g*8 + i) * Dn] = u;
            float bu = bb * u;
            lf = a * lf + bu;
            P  = fmaf(ap, bu, P);
            ap *= a;
        }
        #pragma unroll
        for (int dh = 0; dh < 3; dh++) { cA[dh] = seq[dh][8]; cB[dh] = seq[dh][9]; }
    }
    g_fin[0][0][b][h][c] = lf;
    g_fin[0][1][b][h][c] = P;
}

// =============== K3a: col-orientation local finals (float2) ==================
// grid (NCH, Bn), 128 thr (2 ch/thread)
__global__ __launch_bounds__(128) void k_scanA_col(
    const float* __restrict__ a_logit, const float* __restrict__ ssm_b)
{
    int c = threadIdx.x * 2;
    int j = blockIdx.x, b = blockIdx.y;
    float2 al = *(const float2*)(a_logit + c);
    float ax = fminf(fmaxf(sigmoidf_(al.x), 1e-4f), 1.f - 1e-4f);
    float ay = fminf(fmaxf(sigmoidf_(al.y), 1e-4f), 1.f - 1e-4f);
    float2 bb = *(const float2*)(ssm_b + c);

    size_t base = ((size_t)b*Hn*Wn + (size_t)j) * Dn + c;
    const size_t stride = (size_t)Wn * Dn;

    float lfx=0.f, lfy=0.f, Px=0.f, Py=0.f, apx=1.f, apy=1.f;
    for (int g = 0; g < 12; g++) {
        float2 t[8];
        #pragma unroll
        for (int i = 0; i < 8; i++) t[i] = *(const float2*)(g_u + base + (size_t)(g*8 + i)*stride);
        #pragma unroll
        for (int i = 0; i < 8; i++) {
            float bux = bb.x * t[i].x, buy = bb.y * t[i].y;
            lfx = ax*lfx + bux;  lfy = ay*lfy + buy;
            Px = fmaf(apx, bux, Px); Py = fmaf(apy, buy, Py);
            apx *= ax; apy *= ay;
        }
    }
    *(float2*)&g_fin[1][0][b][j][c] = make_float2(lfx, lfy);
    *(float2*)&g_fin[1][1][b][j][c] = make_float2(Px, Py);
}

// =============== K3b: chunk-level carry scans (float2) ========================
__global__ __launch_bounds__(128) void k_scanB(const float* __restrict__ a_logit)
{
    int c = threadIdx.x * 2;
    int b = blockIdx.x, o = blockIdx.y;
    float2 al = *(const float2*)(a_logit + c);
    float ax = fminf(fmaxf(sigmoidf_(al.x), 1e-4f), 1.f - 1e-4f);
    float ay = fminf(fmaxf(sigmoidf_(al.y), 1e-4f), 1.f - 1e-4f);
    float a96x = (float)exp(96.0 * log((double)ax));
    float a96y = (float)exp(96.0 * log((double)ay));

    float cx = 0.f, cy = 0.f;
    for (int g = 0; g < 8; g++) {
        float2 t[12];
        #pragma unroll
        for (int i = 0; i < 12; i++) t[i] = *(const float2*)&g_fin[o][0][b][g*12 + i][c];
        #pragma unroll
        for (int i = 0; i < 12; i++) {
            *(float2*)&g_carry[o][0][b][g*12 + i][c] = make_float2(cx, cy);
            cx = a96x*cx + t[i].x;  cy = a96y*cy + t[i].y;
        }
    }
    cx = 0.f; cy = 0.f;
    for (int g = 7; g >= 0; g--) {
        float2 t[12];
        #pragma unroll
        for (int i = 0; i < 12; i++) t[i] = *(const float2*)&g_fin[o][1][b][g*12 + i][c];
        #pragma unroll
        for (int i = 11; i >= 0; i--) {
            *(float2*)&g_carry[o][1][b][g*12 + i][c] = make_float2(cx, cy);
            cx = a96x*cx + t[i].x;  cy = a96y*cy + t[i].y;
        }
    }
}

// =============== K3c: apply pass (float2); o==1 fuses gate + bf16 split ======
__global__ __launch_bounds__(128) void k_scanC(
    const float* __restrict__ a_logit, const float* __restrict__ ssm_b,
    const float* __restrict__ ssm_c,  const float* __restrict__ ssm_d, int o)
{
    int c = threadIdx.x * 2;
    int j = blockIdx.x, b = blockIdx.y;
    float2 al = *(const float2*)(a_logit + c);
    float ax = fminf(fmaxf(sigmoidf_(al.x), 1e-4f), 1.f - 1e-4f);
    float ay = fminf(fmaxf(sigmoidf_(al.y), 1e-4f), 1.f - 1e-4f);
    float invax = 1.f/ax, invay = 1.f/ay;
    float a96x = (float)exp(96.0 * log((double)ax));
    float a96y = (float)exp(96.0 * log((double)ay));
    float2 bb = *(const float2*)(ssm_b + c);
    float2 cc = *(const float2*)(ssm_c + c);
    float2 dd = *(const float2*)(ssm_d + c);

    float2 sf = *(const float2*)&g_carry[o][0][b][j][c];
    float2 cb = *(const float2*)&g_carry[o][1][b][j][c];
    float cb96x = a96x * cb.x, cb96y = a96y * cb.y;
    float2 Tt = *(const float2*)&g_fin[o][1][b][j][c];

    size_t base, stride;
    if (o == 0) { base = ((size_t)(b*Hn + j) * Wn) * Dn + c;      stride = Dn; }
    else        { base = ((size_t)b*Hn*Wn + (size_t)j) * Dn + c;  stride = (size_t)Wn * Dn; }

    float Px=0.f, Py=0.f, apx=1.f, apy=1.f, rapx=1.f, rapy=1.f;
    for (int g = 0; g < 12; g++) {
        float2 t[8], yv[8], gv[8];
        #pragma unroll
        for (int i = 0; i < 8; i++) t[i] = *(const float2*)(g_u + base + (size_t)(g*8 + i)*stride);
        if (o == 1) {
            #pragma unroll
            for (int i = 0; i < 8; i++) yv[i] = *(const float2*)(g_y + base + (size_t)(g*8 + i)*stride);
            #pragma unroll
            for (int i = 0; i < 8; i++) gv[i] = *(const float2*)(g_gate + base + (size_t)(g*8 + i)*stride);
        }
        #pragma unroll
        for (int i = 0; i < 8; i++) {
            size_t addr = base + (size_t)(g*8 + i) * stride;
            float uxx = t[i].x, uyy = t[i].y;
            sf.x = ax*sf.x + bb.x*uxx;
            sf.y = ay*sf.y + bb.y*uyy;
            float sbx = (Tt.x - Px + cb96x) * rapx;
            float sby = (Tt.y - Py + cb96y) * rapy;
            float ctx = 0.25f * cc.x * (sf.x + sbx);
            float cty = 0.25f * cc.y * (sf.y + sby);
            if (o == 0) {
                float2 ov = {ctx + dd.x*uxx, cty + dd.y*uyy};
                *(float2*)(g_y + addr) = ov;
            } else {
                float fvx = (yv[i].x + ctx) * gv[i].x;
                float fvy = (yv[i].y + cty) * gv[i].y;
                bf16 hx = __float2bfloat16(fvx), hy = __float2bfloat16(fvy);
                uint32_t hp = ((uint32_t)__bfloat16_as_ushort(hy)<<16) | __bfloat16_as_ushort(hx);
                bf16 lx = __float2bfloat16(fvx - __bfloat162float(hx));
                bf16 ly = __float2bfloat16(fvy - __bfloat162float(hy));
                uint32_t lp = ((uint32_t)__bfloat16_as_ushort(ly)<<16) | __bfloat16_as_ushort(lx);
                *(uint32_t*)(g_ahi + addr) = hp;
                *(uint32_t*)(g_alo + addr) = lp;
            }
            Px = fmaf(apx, bb.x*uxx, Px);
            Py = fmaf(apy, bb.y*uyy, Py);
            apx *= ax; apy *= ay;
            rapx *= invax; rapy *= invay;
        }
    }
}

// ==============================================================================
extern "C" void kernel_launch(void* const* d_in, const int* in_sizes, int n_in,
                              void* d_out, int out_size)
{
    const float* x       = (const float*)d_in[0];
    const float* ln_g    = (const float*)d_in[1];
    const float* ln_b    = (const float*)d_in[2];
    const float* w_in    = (const float*)d_in[3];
    const float* b_in    = (const float*)d_in[4];
    const float* conv_w  = (const float*)d_in[5];
    const float* conv_b  = (const float*)d_in[6];
    const float* a_logit = (const float*)d_in[7];
    const float* ssm_b   = (const float*)d_in[8];
    const float* ssm_c   = (const float*)d_in[9];
    const float* ssm_d   = (const float*)d_in[10];
    const float* w_out   = (const float*)d_in[11];
    const float* b_out   = (const float*)d_in[12];
    float* out = (float*)d_out;

    cudaFuncSetAttribute(k_gemm, cudaFuncAttributeMaxDynamicSharedMemorySize, SMEM_GEMM);

    k_wsplit<<<768, 256>>>(w_in, w_out);
    k_ln_split<<<NPIX/32, 256>>>(x, ln_g, ln_b);
    k_gemm<<<dim3(4, NPIX/128), 256, SMEM_GEMM>>>(0, b_in, nullptr, nullptr);
    k_conv_rowscan<<<Bn*Hn, 256>>>(conv_w, conv_b, a_logit, ssm_b);
    k_scanA_col<<<dim3(NCH, Bn), 128>>>(a_logit, ssm_b);
    k_scanB<<<dim3(Bn, 2), 128>>>(a_logit);
    k_scanC<<<dim3(NCH, Bn), 128>>>(a_logit, ssm_b, ssm_c, ssm_d, 0);
    k_scanC<<<dim3(NCH, Bn), 128>>>(a_logit, ssm_b, ssm_c, ssm_d, 1);
    k_gemm<<<dim3(2, NPIX/128), 256, SMEM_GEMM>>>(1, b_out, x, out);
}